// round 8
// baseline (speedup 1.0000x reference)
#include <cuda_runtime.h>
#include <cuda_fp16.h>

// Problem constants
#define NXv 128
#define NYv 128
#define NZv 8
#define NVOX (NXv * NYv * NZv)   // 131072
#define NVIEW 6
#define NCH 64
#define HFv 116
#define WFv 200
#define FEAT_HW (HFv * WFv)      // 23200
#define IMG_W 1600.0f
#define IMG_H 928.0f

// Channel-last fp16 scratch: [V, HF, WF, C]  (17.8 MB). One tap = 128B line.
__device__ __align__(256) static __half g_feat_h[NVIEW * FEAT_HW * NCH];

// ---------------------------------------------------------------------------
// Kernel 1: transpose+convert [V,C,H,W] fp32 -> [V,H,W,C] fp16.
// ---------------------------------------------------------------------------
__global__ __launch_bounds__(256)
void convert_kernel(const float* __restrict__ xfov)
{
    __shared__ float tile[NCH][33];

    const int w0 = blockIdx.x * 32;
    const int vh = blockIdx.y;            // 0..695
    const int v  = vh / HFv;
    const int h  = vh - v * HFv;

    const int tx = threadIdx.x & 31;
    const int ty = threadIdx.x >> 5;      // 0..7

    const int w = w0 + tx;
    if (w < WFv) {
#pragma unroll
        for (int i = 0; i < 8; i++) {
            const int c = ty + i * 8;
            tile[c][tx] = xfov[((size_t)(v * NCH + c) * HFv + h) * WFv + w];
        }
    }
    __syncthreads();

    __half2* dst = (__half2*)g_feat_h;
#pragma unroll
    for (int j = 0; j < 4; j++) {
        const int ww = w0 + ty + 8 * j;
        if (ww < WFv) {
            const float a = tile[2 * tx + 0][ty + 8 * j];
            const float b = tile[2 * tx + 1][ty + 8 * j];
            dst[(size_t)(v * FEAT_HW + h * WFv + ww) * (NCH / 2) + tx] =
                __floats2half2_rn(a, b);
        }
    }
}

// ---------------------------------------------------------------------------
// Kernel 2: gather. 4 threads/point (16 ch each), branchless over views.
// All 6 descriptors computed independently, then 48 unconditional LDG.128.
// Invalid views: off=0 (broadcast line), weights FSEL'd to zero.
// ---------------------------------------------------------------------------
__device__ __forceinline__ void hcomb(float* acc,
                                      const uint4& a00, const uint4& a10,
                                      const uint4& a01, const uint4& a11,
                                      __half2 w00, __half2 w10,
                                      __half2 w01, __half2 w11)
{
    const __half2* f00 = (const __half2*)&a00;
    const __half2* f10 = (const __half2*)&a10;
    const __half2* f01 = (const __half2*)&a01;
    const __half2* f11 = (const __half2*)&a11;
#pragma unroll
    for (int k = 0; k < 4; k++) {
        __half2 s = __hmul2(f00[k], w00);
        s = __hfma2(f10[k], w10, s);
        s = __hfma2(f01[k], w01, s);
        s = __hfma2(f11[k], w11, s);
        const float2 sf = __half22float2(s);
        acc[2 * k + 0] += sf.x;
        acc[2 * k + 1] += sf.y;
    }
}

__global__ __launch_bounds__(256)
void gather_kernel(const float* __restrict__ points,
                   const float* __restrict__ proj,
                   float* __restrict__ out)
{
    __shared__ float sM[NVIEW * 16];
    if (threadIdx.x < NVIEW * 16) sM[threadIdx.x] = proj[threadIdx.x];
    __syncthreads();

    const int t = blockIdx.x * blockDim.x + threadIdx.x; // 0..524287
    const int p = t >> 2;                                // voxel (output-linear)
    const int q = t & 3;                                 // channel quarter

    const int z = p & (NZv - 1);
    const int y = (p >> 3) & (NYv - 1);
    const int x = p >> 10;
    const int n = (z * NYv + y) * NXv + x;

    const float pxw = __ldg(points + n * 3 + 0);
    const float pyw = __ldg(points + n * 3 + 1);
    const float pzw = __ldg(points + n * 3 + 2);

    // --- Phase A: all 6 view descriptors (independent math, no branches) ---
    unsigned off[NVIEW];
    __half2  hA[NVIEW];   // (w00, w10)
    __half2  hB[NVIEW];   // (w01, w11)
    int cnt = 0;

#pragma unroll
    for (int v = 0; v < NVIEW; v++) {
        const float* M = &sM[v * 16];
        const float cx = fmaf(M[0], pxw, fmaf(M[1], pyw, fmaf(M[2],  pzw, M[3])));
        const float cy = fmaf(M[4], pxw, fmaf(M[5], pyw, fmaf(M[6],  pzw, M[7])));
        const float d  = fmaf(M[8], pxw, fmaf(M[9], pyw, fmaf(M[10], pzw, M[11])));

        const float ds = (fabsf(d) > 1e-6f) ? d : 1e-6f;
        const float r  = __fdividef(1.0f, ds);
        const float u  = cx * r;
        const float vv = cy * r;

        const bool valid = (d > 0.0f) & (u > 0.0f) & (u < IMG_W)
                                      & (vv > 0.0f) & (vv < IMG_H);
        cnt += valid;

        // Exact power-of-2 scale: WF/IMG_W = HF/IMG_H = 0.125
        const float fx = fmaf(u,  0.125f, -0.5f);   // valid => (-0.5, 199.5)
        const float fy = fmaf(vv, 0.125f, -0.5f);   // valid => (-0.5, 115.5)
        const float x0f = floorf(fx);
        const float y0f = floorf(fy);
        const int x0 = (int)x0f;
        const int y0 = (int)y0f;
        const float wx1 = fx - x0f;
        const float wy1 = fy - y0f;

        // Base clamped so all 4 taps are in-bounds (also sanitizes garbage
        // coords from invalid views); edge handling folded into weights.
        const int bx = min(max(x0, 0), WFv - 2);
        const int by = min(max(y0, 0), HFv - 2);
        float wl = (x0 < 0) ? wx1 : ((x0 >= WFv - 1) ? 0.0f : 1.0f - wx1);
        float wr = (x0 < 0) ? 0.0f : ((x0 >= WFv - 1) ? 1.0f - wx1 : wx1);
        float wt = (y0 < 0) ? wy1 : ((y0 >= HFv - 1) ? 0.0f : 1.0f - wy1);
        float wb = (y0 < 0) ? 0.0f : ((y0 >= HFv - 1) ? 1.0f - wy1 : wy1);

        // FSEL (not multiply) so NaN garbage from invalid views is squashed.
        wl = valid ? wl : 0.0f;
        wr = valid ? wr : 0.0f;
        wt = valid ? wt : 0.0f;
        wb = valid ? wb : 0.0f;

        hA[v] = __floats2half2_rn(wl * wt, wr * wt);
        hB[v] = __floats2half2_rn(wl * wb, wr * wb);
        // Invalid views read line 0 -> warp-broadcast, near-free.
        off[v] = valid ? (unsigned)((v * FEAT_HW + by * WFv + bx) * NCH) : 0u;
    }

    // --- Phase B: 48 unconditional loads + fp16 tap-combine ---
    float acc[16];
#pragma unroll
    for (int i = 0; i < 16; i++) acc[i] = 0.0f;

#pragma unroll
    for (int v = 0; v < NVIEW; v++) {
        const __half* bp = g_feat_h + off[v] + q * 16;

        const uint4 a00 = __ldg((const uint4*)(bp));
        const uint4 b00 = __ldg((const uint4*)(bp + 8));
        const uint4 a10 = __ldg((const uint4*)(bp + NCH));
        const uint4 b10 = __ldg((const uint4*)(bp + NCH + 8));
        const uint4 a01 = __ldg((const uint4*)(bp + WFv * NCH));
        const uint4 b01 = __ldg((const uint4*)(bp + WFv * NCH + 8));
        const uint4 a11 = __ldg((const uint4*)(bp + (WFv + 1) * NCH));
        const uint4 b11 = __ldg((const uint4*)(bp + (WFv + 1) * NCH + 8));

        const __half2 hw00 = __low2half2(hA[v]);
        const __half2 hw10 = __high2half2(hA[v]);
        const __half2 hw01 = __low2half2(hB[v]);
        const __half2 hw11 = __high2half2(hB[v]);

        hcomb(acc + 0, a00, a10, a01, a11, hw00, hw10, hw01, hw11);
        hcomb(acc + 8, b00, b10, b01, b11, hw00, hw10, hw01, hw11);
    }

    const float inv = (cnt > 0) ? (1.0f / (float)cnt) : 0.0f;
    const int cbase = q * 16;
#pragma unroll
    for (int j = 0; j < 16; j++) {
        out[(size_t)(cbase + j) * NVOX + p] = acc[j] * inv;
    }
}

extern "C" void kernel_launch(void* const* d_in, const int* in_sizes, int n_in,
                              void* d_out, int out_size)
{
    const float* x_fov  = (const float*)d_in[0];  // [1,6,64,116,200]
    const float* points = (const float*)d_in[1];  // [131072,3]
    const float* proj   = (const float*)d_in[2];  // [6,4,4]
    float* out = (float*)d_out;                   // [1,64,128,128,8]

    {
        dim3 blk(256);
        dim3 grd((WFv + 31) / 32, NVIEW * HFv);   // (7, 696)
        convert_kernel<<<grd, blk>>>(x_fov);
    }
    {
        const int threads = 256;
        const int blocks  = (NVOX * 4) / threads; // 2048
        gather_kernel<<<blocks, threads>>>(points, proj, out);
    }
}

// round 9
// speedup vs baseline: 1.1562x; 1.1562x over previous
#include <cuda_runtime.h>
#include <cuda_fp16.h>

// Problem constants
#define NXv 128
#define NYv 128
#define NZv 8
#define NVOX (NXv * NYv * NZv)   // 131072
#define NVIEW 6
#define NCH 64
#define HFv 116
#define WFv 200
#define FEAT_HW (HFv * WFv)      // 23200
#define IMG_W 1600.0f
#define IMG_H 928.0f

// Channel-last fp16 scratch: [V, HF, WF, C]  (17.8 MB). One tap = 128B line.
__device__ __align__(256) static __half g_feat_h[NVIEW * FEAT_HW * NCH];

// ---------------------------------------------------------------------------
// Kernel 1: transpose+convert [V,C,H,W] fp32 -> [V,H,W,C] fp16.
// ---------------------------------------------------------------------------
__global__ __launch_bounds__(256)
void convert_kernel(const float* __restrict__ xfov)
{
    __shared__ float tile[NCH][33];

    const int w0 = blockIdx.x * 32;
    const int vh = blockIdx.y;            // 0..695
    const int v  = vh / HFv;
    const int h  = vh - v * HFv;

    const int tx = threadIdx.x & 31;
    const int ty = threadIdx.x >> 5;      // 0..7

    const int w = w0 + tx;
    if (w < WFv) {
#pragma unroll
        for (int i = 0; i < 8; i++) {
            const int c = ty + i * 8;
            tile[c][tx] = xfov[((size_t)(v * NCH + c) * HFv + h) * WFv + w];
        }
    }
    __syncthreads();

    __half2* dst = (__half2*)g_feat_h;
#pragma unroll
    for (int j = 0; j < 4; j++) {
        const int ww = w0 + ty + 8 * j;
        if (ww < WFv) {
            const float a = tile[2 * tx + 0][ty + 8 * j];
            const float b = tile[2 * tx + 1][ty + 8 * j];
            dst[(size_t)(v * FEAT_HW + h * WFv + ww) * (NCH / 2) + tx] =
                __floats2half2_rn(a, b);
        }
    }
}

// ---------------------------------------------------------------------------
// Kernel 2: gather. 2 threads/point (32 ch each), R5 structure:
// per-thread projection, skip invalid views, fp16 view accumulation.
// ---------------------------------------------------------------------------
__global__ __launch_bounds__(256)
void gather_kernel(const float* __restrict__ points,
                   const float* __restrict__ proj,
                   float* __restrict__ out)
{
    __shared__ float sM[NVIEW * 16];
    if (threadIdx.x < NVIEW * 16) sM[threadIdx.x] = proj[threadIdx.x];
    __syncthreads();

    const int t    = blockIdx.x * blockDim.x + threadIdx.x; // 0..262143
    const int p    = t >> 1;                                // voxel (output-linear)
    const int half = t & 1;                                 // channel half

    const int z = p & (NZv - 1);
    const int y = (p >> 3) & (NYv - 1);
    const int x = p >> 10;
    const int n = (z * NYv + y) * NXv + x;

    const float pxw = __ldg(points + n * 3 + 0);
    const float pyw = __ldg(points + n * 3 + 1);
    const float pzw = __ldg(points + n * 3 + 2);

    __half2 acc2[16];
#pragma unroll
    for (int i = 0; i < 16; i++) acc2[i] = __float2half2_rn(0.0f);
    int cnt = 0;

    const int coff = half * 32;  // channel offset in halves

#pragma unroll 1
    for (int v = 0; v < NVIEW; v++) {
        const float* M = &sM[v * 16];
        const float cx = fmaf(M[0], pxw, fmaf(M[1], pyw, fmaf(M[2],  pzw, M[3])));
        const float cy = fmaf(M[4], pxw, fmaf(M[5], pyw, fmaf(M[6],  pzw, M[7])));
        const float d  = fmaf(M[8], pxw, fmaf(M[9], pyw, fmaf(M[10], pzw, M[11])));

        const float ds = (fabsf(d) > 1e-6f) ? d : 1e-6f;
        const float r  = __fdividef(1.0f, ds);
        const float u  = cx * r;
        const float vv = cy * r;

        const bool valid = (d > 0.0f) & (u > 0.0f) & (u < IMG_W)
                                      & (vv > 0.0f) & (vv < IMG_H);
        if (!valid) continue;

        // Exact power-of-2 scale: WF/IMG_W = HF/IMG_H = 0.125
        const float fx = fmaf(u,  0.125f, -0.5f);   // (-0.5, 199.5)
        const float fy = fmaf(vv, 0.125f, -0.5f);   // (-0.5, 115.5)
        const float x0f = floorf(fx);
        const float y0f = floorf(fy);
        const int x0 = (int)x0f;   // [-1, 199]
        const int y0 = (int)y0f;   // [-1, 115]
        const float wx1 = fx - x0f;
        const float wy1 = fy - y0f;

        // Base clamped so all 4 taps are in-bounds; edge handling folded
        // into weights (identical to zero-padded bilinear).
        const int bx = min(max(x0, 0), WFv - 2);
        const int by = min(max(y0, 0), HFv - 2);
        const float wl = (x0 < 0) ? wx1 : ((x0 >= WFv - 1) ? 0.0f : 1.0f - wx1);
        const float wr = (x0 < 0) ? 0.0f : ((x0 >= WFv - 1) ? 1.0f - wx1 : wx1);
        const float wt = (y0 < 0) ? wy1 : ((y0 >= HFv - 1) ? 0.0f : 1.0f - wy1);
        const float wb = (y0 < 0) ? 0.0f : ((y0 >= HFv - 1) ? 1.0f - wy1 : wy1);

        const __half2 hw00 = __float2half2_rn(wl * wt);
        const __half2 hw10 = __float2half2_rn(wr * wt);
        const __half2 hw01 = __float2half2_rn(wl * wb);
        const __half2 hw11 = __float2half2_rn(wr * wb);

        const __half* bp = g_feat_h + (unsigned)((v * FEAT_HW + by * WFv + bx) * NCH) + coff;

        // 16 independent LDG.128: 4 taps x 32 channels
        uint4 t00[4], t10[4], t01[4], t11[4];
#pragma unroll
        for (int i = 0; i < 4; i++) {
            t00[i] = __ldg((const uint4*)(bp) + i);
            t10[i] = __ldg((const uint4*)(bp + NCH) + i);
            t01[i] = __ldg((const uint4*)(bp + WFv * NCH) + i);
            t11[i] = __ldg((const uint4*)(bp + (WFv + 1) * NCH) + i);
        }

        const __half2* f00 = (const __half2*)t00;
        const __half2* f10 = (const __half2*)t10;
        const __half2* f01 = (const __half2*)t01;
        const __half2* f11 = (const __half2*)t11;
#pragma unroll
        for (int k = 0; k < 16; k++) {
            __half2 s = __hmul2(f00[k], hw00);
            s = __hfma2(f10[k], hw10, s);
            s = __hfma2(f01[k], hw01, s);
            s = __hfma2(f11[k], hw11, s);
            acc2[k] = __hadd2(acc2[k], s);
        }
        cnt++;
    }

    const float inv = (cnt > 0) ? (1.0f / (float)cnt) : 0.0f;
    const int cbase = half * 32;
#pragma unroll
    for (int k = 0; k < 16; k++) {
        const float2 sf = __half22float2(acc2[k]);
        out[(size_t)(cbase + 2 * k + 0) * NVOX + p] = sf.x * inv;
        out[(size_t)(cbase + 2 * k + 1) * NVOX + p] = sf.y * inv;
    }
}

extern "C" void kernel_launch(void* const* d_in, const int* in_sizes, int n_in,
                              void* d_out, int out_size)
{
    const float* x_fov  = (const float*)d_in[0];  // [1,6,64,116,200]
    const float* points = (const float*)d_in[1];  // [131072,3]
    const float* proj   = (const float*)d_in[2];  // [6,4,4]
    float* out = (float*)d_out;                   // [1,64,128,128,8]

    {
        dim3 blk(256);
        dim3 grd((WFv + 31) / 32, NVIEW * HFv);   // (7, 696)
        convert_kernel<<<grd, blk>>>(x_fov);
    }
    {
        const int threads = 256;
        const int blocks  = (NVOX * 2) / threads; // 1024
        gather_kernel<<<blocks, threads>>>(points, proj, out);
    }
}